// round 3
// baseline (speedup 1.0000x reference)
#include <cuda_runtime.h>
#include <math.h>

#define Bz 4
#define Sz 4096
#define Hz 2048
#define Ez 16
#define EDz 512
#define ROWS_PER_BLK 32
#define K1_BLOCKS ((Bz * Sz) / ROWS_PER_BLK) /* 512 */
#define LN_EPS 1e-5f
#define NEG_INF -1e9f

// ---- scratch (no allocations allowed) ----
__device__ float g_partial[K1_BLOCKS * Hz]; // per-block LN-mean partial sums (4 MB)
__device__ float g_qin[Bz * Hz];            // query_input
__device__ float g_q[Bz * Hz];              // q
__device__ float g_k[Ez * Hz];              // k

// ============================================================
// K1: fused LayerNorm + mean-over-S partial accumulation.
// One pass over hidden_states (128 MB). Each block handles 32 rows
// of one batch; each thread owns 8 fixed h-slots (two float4s).
// ============================================================
__global__ __launch_bounds__(256) void k1_ln_mean(const float* __restrict__ x) {
    const int tid  = threadIdx.x;
    const int lane = tid & 31;
    const int warp = tid >> 5;
    __shared__ float2 wred[8];
    __shared__ float2 stat; // (mu, rsigma)

    float acc[8] = {0.f, 0.f, 0.f, 0.f, 0.f, 0.f, 0.f, 0.f};
    const long long row0 = (long long)blockIdx.x * ROWS_PER_BLK;

    for (int r = 0; r < ROWS_PER_BLK; ++r) {
        const float4* row = (const float4*)(x + (row0 + r) * Hz);
        float4 v0 = row[tid];
        float4 v1 = row[256 + tid];

        float s  = v0.x + v0.y + v0.z + v0.w + v1.x + v1.y + v1.z + v1.w;
        float ss = v0.x * v0.x + v0.y * v0.y + v0.z * v0.z + v0.w * v0.w
                 + v1.x * v1.x + v1.y * v1.y + v1.z * v1.z + v1.w * v1.w;
        #pragma unroll
        for (int o = 16; o; o >>= 1) {
            s  += __shfl_down_sync(0xffffffffu, s,  o);
            ss += __shfl_down_sync(0xffffffffu, ss, o);
        }
        if (lane == 0) wred[warp] = make_float2(s, ss);
        __syncthreads();
        if (warp == 0) {
            float2 t = (lane < 8) ? wred[lane] : make_float2(0.f, 0.f);
            #pragma unroll
            for (int o = 4; o; o >>= 1) {
                t.x += __shfl_down_sync(0xffffffffu, t.x, o);
                t.y += __shfl_down_sync(0xffffffffu, t.y, o);
            }
            if (lane == 0) {
                float mu  = t.x * (1.0f / Hz);
                float var = t.y * (1.0f / Hz) - mu * mu;
                stat = make_float2(mu, rsqrtf(var + LN_EPS));
            }
        }
        __syncthreads();
        const float mu = stat.x, rs = stat.y;
        acc[0] += (v0.x - mu) * rs; acc[1] += (v0.y - mu) * rs;
        acc[2] += (v0.z - mu) * rs; acc[3] += (v0.w - mu) * rs;
        acc[4] += (v1.x - mu) * rs; acc[5] += (v1.y - mu) * rs;
        acc[6] += (v1.z - mu) * rs; acc[7] += (v1.w - mu) * rs;
    }
    float4* out = (float4*)(g_partial + (long long)blockIdx.x * Hz);
    out[tid]       = make_float4(acc[0], acc[1], acc[2], acc[3]);
    out[256 + tid] = make_float4(acc[4], acc[5], acc[6], acc[7]);
}

// ============================================================
// K2: reduce 128 partial slabs per batch -> hidden_mean,
// build query_input = layer_emb[cl] + gamma*mean + beta
// ============================================================
__global__ __launch_bounds__(256) void k2_reduce(const float* __restrict__ le,
                                                 const float* __restrict__ gamma,
                                                 const float* __restrict__ beta,
                                                 const int* __restrict__ cur) {
    const int b = blockIdx.y;
    const int h = blockIdx.x * 256 + threadIdx.x;
    const float* p = g_partial + (long long)(b * 128) * Hz + h;
    float s = 0.f;
    #pragma unroll 8
    for (int kk = 0; kk < 128; ++kk) s += p[(long long)kk * Hz];
    const int cl = *cur;
    g_qin[b * Hz + h] = le[cl * Hz + h] + gamma[h] * (s * (1.0f / Sz)) + beta[h];
}

// ============================================================
// K3q: q[b][j] = qin[b]·Wq[j] + bq[j].  One warp per output j.
// ============================================================
__global__ __launch_bounds__(256) void k3_q(const float* __restrict__ Wq,
                                            const float* __restrict__ bq) {
    __shared__ float sq[Bz * Hz]; // 32 KB
    const int tid = threadIdx.x;
    for (int i = tid; i < (Bz * Hz) / 4; i += 256)
        ((float4*)sq)[i] = ((const float4*)g_qin)[i];
    __syncthreads();

    const int warp = tid >> 5, lane = tid & 31;
    const int j = blockIdx.x * 8 + warp;
    const float4* wrow = (const float4*)(Wq + (long long)j * Hz);
    float a0 = 0.f, a1 = 0.f, a2 = 0.f, a3 = 0.f;
    #pragma unroll 4
    for (int i = 0; i < 16; ++i) {
        const int h4 = i * 32 + lane;
        float4 w  = wrow[h4];
        float4 x0 = ((float4*)sq)[0 * 512 + h4];
        float4 x1 = ((float4*)sq)[1 * 512 + h4];
        float4 x2 = ((float4*)sq)[2 * 512 + h4];
        float4 x3 = ((float4*)sq)[3 * 512 + h4];
        a0 += w.x * x0.x + w.y * x0.y + w.z * x0.z + w.w * x0.w;
        a1 += w.x * x1.x + w.y * x1.y + w.z * x1.z + w.w * x1.w;
        a2 += w.x * x2.x + w.y * x2.y + w.z * x2.z + w.w * x2.w;
        a3 += w.x * x3.x + w.y * x3.y + w.z * x3.z + w.w * x3.w;
    }
    #pragma unroll
    for (int o = 16; o; o >>= 1) {
        a0 += __shfl_down_sync(0xffffffffu, a0, o);
        a1 += __shfl_down_sync(0xffffffffu, a1, o);
        a2 += __shfl_down_sync(0xffffffffu, a2, o);
        a3 += __shfl_down_sync(0xffffffffu, a3, o);
    }
    if (lane == 0) {
        const float bb = bq[j];
        g_q[0 * Hz + j] = a0 + bb;
        g_q[1 * Hz + j] = a1 + bb;
        g_q[2 * Hz + j] = a2 + bb;
        g_q[3 * Hz + j] = a3 + bb;
    }
}

// ============================================================
// K3k: k[e][j] = (le[e]+ce[e])·Wk[j] + bk[j]. Warp per j, 16 accs,
// layer_features tiled through 32 KB smem.
// ============================================================
__global__ __launch_bounds__(256) void k3_k(const float* __restrict__ le,
                                            const float* __restrict__ ce,
                                            const float* __restrict__ Wk,
                                            const float* __restrict__ bkv) {
    __shared__ float lf[Ez * 512]; // 32 KB tile
    const int tid = threadIdx.x, warp = tid >> 5, lane = tid & 31;
    const int j = blockIdx.x * 8 + warp;
    float acc[Ez];
    #pragma unroll
    for (int e = 0; e < Ez; ++e) acc[e] = 0.f;

    for (int t = 0; t < 4; ++t) {
        __syncthreads();
        for (int i = tid; i < (Ez * 512) / 4; i += 256) {
            const int e = i >> 7, c = i & 127;
            float4 a = ((const float4*)(le + e * Hz + t * 512))[c];
            float4 b = ((const float4*)(ce + e * Hz + t * 512))[c];
            ((float4*)lf)[i] = make_float4(a.x + b.x, a.y + b.y, a.z + b.z, a.w + b.w);
        }
        __syncthreads();
        const float4* wrow = (const float4*)(Wk + (long long)j * Hz + t * 512);
        #pragma unroll
        for (int i = 0; i < 4; ++i) {
            const int h4 = i * 32 + lane;
            float4 w = wrow[h4];
            #pragma unroll
            for (int e = 0; e < Ez; ++e) {
                float4 v = ((float4*)lf)[e * 128 + h4];
                acc[e] += w.x * v.x + w.y * v.y + w.z * v.z + w.w * v.w;
            }
        }
    }
    #pragma unroll
    for (int e = 0; e < Ez; ++e) {
        #pragma unroll
        for (int o = 16; o; o >>= 1)
            acc[e] += __shfl_down_sync(0xffffffffu, acc[e], o);
    }
    if (lane == 0) {
        const float bb = bkv[j];
        #pragma unroll
        for (int e = 0; e < Ez; ++e) g_k[e * Hz + j] = acc[e] + bb;
    }
}

// ============================================================
// K4: attention dots, spatial bias, folded edge bias, softmax,
// KL routing loss, argmax, output writes. Single block.
// ============================================================
__global__ __launch_bounds__(512) void k4_final(const float* __restrict__ sp,
                                                const float* __restrict__ ee,
                                                const int* __restrict__ cur,
                                                const int* __restrict__ avail,
                                                float* __restrict__ out,
                                                int out_size) {
    __shared__ float att[Bz * Ez];
    __shared__ float u[EDz];
    __shared__ float ebias[Ez];
    __shared__ float sc[Bz * Ez];
    const int tid = threadIdx.x, warp = tid >> 5, lane = tid & 31;
    const int cl = *cur;

    // folded edge vector: u = sum_i avail_i*(i!=cl)/max(|i-cl|,1) * edge[i]
    {
        float uv = 0.f;
        #pragma unroll
        for (int i = 0; i < Ez; ++i) {
            if (avail[i] != 0 && i != cl) {
                int d = i > cl ? i - cl : cl - i;
                if (d < 1) d = 1;
                uv += (1.0f / (float)d) * ee[i * EDz + tid];
            }
        }
        u[tid] = uv;
    }

    // attention[b][e] = q[b]·k[e] / sqrt(H)
    const float iscale = 1.0f / sqrtf((float)Hz);
    for (int d = warp; d < Bz * Ez; d += 16) {
        const int b = d >> 4, e = d & 15;
        const float4* qq = (const float4*)(g_q + b * Hz);
        const float4* kk = (const float4*)(g_k + e * Hz);
        float a = 0.f;
        for (int i = lane; i < Hz / 4; i += 32) {
            float4 qv = qq[i];
            float4 kv = kk[i];
            a += qv.x * kv.x + qv.y * kv.y + qv.z * kv.z + qv.w * kv.w;
        }
        #pragma unroll
        for (int o = 16; o; o >>= 1) a += __shfl_down_sync(0xffffffffu, a, o);
        if (lane == 0) att[d] = a * iscale;
    }
    __syncthreads();

    // edge_bias[j] = u · edge[j]
    if (warp < Ez) {
        const int j = warp;
        float a = 0.f;
        for (int i = lane; i < EDz; i += 32) a += u[i] * ee[j * EDz + i];
        #pragma unroll
        for (int o = 16; o; o >>= 1) a += __shfl_down_sync(0xffffffffu, a, o);
        if (lane == 0) ebias[j] = a;
    }
    __syncthreads();

    // scores
    if (tid < Bz * Ez) {
        const int e = tid & 15;
        int d = e > cl ? e - cl : cl - e;
        float s = att[tid] + sp[d] + ebias[e];
        sc[tid] = (avail[e] != 0) ? s : NEG_INF;
    }
    __syncthreads();

    // tiny serial tail: softmax, KL loss, argmax, output
    if (tid == 0) {
        float navail = 0.f;
        for (int e = 0; e < Ez; ++e) navail += (avail[e] != 0) ? 1.0f : 0.0f;
        const float t = 1.0f / navail;
        const float logt = logf(t);
        float probs[Bz * Ez];
        float kl = 0.f;
        for (int b = 0; b < Bz; ++b) {
            float mx = -3.4e38f;
            for (int e = 0; e < Ez; ++e) mx = fmaxf(mx, sc[b * Ez + e]);
            float sum = 0.f;
            float ex[Ez];
            for (int e = 0; e < Ez; ++e) { ex[e] = expf(sc[b * Ez + e] - mx); sum += ex[e]; }
            const float inv = 1.0f / sum;
            for (int e = 0; e < Ez; ++e) {
                float p = ex[e] * inv;
                probs[b * Ez + e] = p;
                float ps = fmaxf(p, 1e-10f);
                kl += t * (logt - logf(ps));
            }
        }
        const float loss = (kl / (float)Bz) * 0.01f;
        int ai = 0; float av = probs[0];
        for (int e = 1; e < Ez; ++e) if (probs[e] > av) { av = probs[e]; ai = e; }

        if (out_size >= 66) {
            out[0] = loss;
            for (int i = 0; i < Bz * Ez; ++i) out[1 + i] = probs[i];
            out[65] = (float)ai;
            for (int i = 66; i < out_size; ++i) out[i] = 0.f;
        } else if (out_size == 65) {
            out[0] = loss;
            for (int i = 0; i < Bz * Ez; ++i) out[1 + i] = probs[i];
        } else if (out_size == 64) {
            for (int i = 0; i < Bz * Ez; ++i) out[i] = probs[i];
        } else if (out_size >= 1) {
            out[0] = loss;
            for (int i = 1; i < out_size && i <= Bz * Ez; ++i) out[i] = probs[i - 1];
        }
    }
}

extern "C" void kernel_launch(void* const* d_in, const int* in_sizes, int n_in,
                              void* d_out, int out_size) {
    const float* hs = (const float*)d_in[0];
    const float* le = (const float*)d_in[1];
    const float* ce = (const float*)d_in[2];
    const float* sp = (const float*)d_in[3];
    const float* ee = (const float*)d_in[4];
    const float* g  = (const float*)d_in[5];
    const float* be = (const float*)d_in[6];
    const float* Wq = (const float*)d_in[7];
    const float* bq = (const float*)d_in[8];
    const float* Wk = (const float*)d_in[9];
    const float* bk = (const float*)d_in[10];
    // d_in[11], d_in[12] = Wv, bv: intentionally unused (dead in reference)
    const int* cl = (const int*)d_in[13];
    const int* av = (const int*)d_in[14];
    float* out = (float*)d_out;

    k1_ln_mean<<<K1_BLOCKS, 256>>>(hs);
    k2_reduce<<<dim3(Hz / 256, Bz), 256>>>(le, g, be, cl);
    k3_q<<<Hz / 8, 256>>>(Wq, bq);
    k3_k<<<Hz / 8, 256>>>(le, ce, Wk, bk);
    k4_final<<<1, 512>>>(sp, ee, cl, av, out, out_size);
}

// round 4
// speedup vs baseline: 1.2260x; 1.2260x over previous
#include <cuda_runtime.h>
#include <math.h>

#define Bz 4
#define Sz 4096
#define Hz 2048
#define Ez 16
#define EDz 512
#define LN_EPS 1e-5f
#define NEG_INF -1e9f

// ---- k1 config: 512 blocks x 4 warps, 8 rows/warp = 16384 rows ----
#define K1_BLOCKS 512
#define K1_WARPS 4
#define ROWS_PER_WARP 8
#define SLABS_PER_B (K1_BLOCKS / Bz) /* 128 */

// ---- k3 config: split-K GEMV, 2 j per warp, chunk=512 floats ----
#define CH 512
#define NCH 4
#define JW 2
#define K3_WARPS 8
#define JB (K3_WARPS * JW)          /* 16 j per block */
#define JG (Hz / JB)                /* 128 j-groups */
#define K3_KBLOCKS (JG * NCH)       /* 512 */
#define K3_BLOCKS (2 * K3_KBLOCKS)  /* 1024: first half K, second half Q */

// ---- scratch ----
__device__ float g_partial[K1_BLOCKS * Hz];       // LN-mean partial slabs (4 MB)
__device__ float g_qin[Bz * Hz];                  // query_input
__device__ float g_lf[Ez * Hz];                   // layer_features = le + ce
__device__ float g_qpart[NCH * Bz * Hz];          // q partials (128 KB)
__device__ float g_kpart[NCH * Ez * Hz];          // k partials (512 KB)
__device__ float g_q[Bz * Hz];
__device__ float g_k[Ez * Hz];

// packed fp32x2 FMA (FFMA2 — PTX-only on sm_103a)
#define FMA2(acc, a, b) \
    asm("fma.rn.f32x2 %0, %1, %2, %0;" : "+l"(acc) : "l"(a), "l"(b))

__device__ __forceinline__ float unpack_sum(unsigned long long v) {
    return __uint_as_float((unsigned)(v & 0xffffffffull)) +
           __uint_as_float((unsigned)(v >> 32));
}

// ============================================================
// K1: warp-per-row fused LayerNorm + mean-over-S accumulation.
// No barriers in the main loop; full row resident in registers.
// ============================================================
__global__ __launch_bounds__(128, 3) void k1_ln_mean(const float* __restrict__ x) {
    const int tid = threadIdx.x, lane = tid & 31, warp = tid >> 5;
    float4 acc[16];
    #pragma unroll
    for (int i = 0; i < 16; ++i) acc[i] = make_float4(0.f, 0.f, 0.f, 0.f);

    const long long row0 = ((long long)blockIdx.x * K1_WARPS + warp) * ROWS_PER_WARP;

    for (int r = 0; r < ROWS_PER_WARP; ++r) {
        const float4* row = (const float4*)(x + (row0 + r) * Hz);
        float4 v[16];
        #pragma unroll
        for (int i = 0; i < 16; ++i) v[i] = row[i * 32 + lane];

        float s = 0.f, ss = 0.f;
        #pragma unroll
        for (int i = 0; i < 16; ++i) {
            s  += v[i].x + v[i].y + v[i].z + v[i].w;
            ss += v[i].x * v[i].x + v[i].y * v[i].y
                + v[i].z * v[i].z + v[i].w * v[i].w;
        }
        #pragma unroll
        for (int o = 16; o; o >>= 1) {
            s  += __shfl_xor_sync(0xffffffffu, s,  o);
            ss += __shfl_xor_sync(0xffffffffu, ss, o);
        }
        const float mu  = s * (1.0f / Hz);
        const float var = ss * (1.0f / Hz) - mu * mu;
        const float rs  = rsqrtf(var + LN_EPS);
        #pragma unroll
        for (int i = 0; i < 16; ++i) {
            acc[i].x += (v[i].x - mu) * rs;
            acc[i].y += (v[i].y - mu) * rs;
            acc[i].z += (v[i].z - mu) * rs;
            acc[i].w += (v[i].w - mu) * rs;
        }
    }

    __shared__ float4 red[K1_WARPS * 512]; // 32 KB
    #pragma unroll
    for (int i = 0; i < 16; ++i) red[warp * 512 + i * 32 + lane] = acc[i];
    __syncthreads();

    float4* gp = (float4*)(g_partial + (long long)blockIdx.x * Hz);
    for (int t = tid; t < 512; t += 128) {
        float4 a = red[t], b = red[512 + t], c = red[1024 + t], d = red[1536 + t];
        gp[t] = make_float4(a.x + b.x + c.x + d.x, a.y + b.y + c.y + d.y,
                            a.z + b.z + c.z + d.z, a.w + b.w + c.w + d.w);
    }
}

// ============================================================
// K2: reduce partial slabs -> g_qin; also build g_lf = le + ce.
// grid (Hz/256, Bz + Ez)
// ============================================================
__global__ __launch_bounds__(256) void k2_prep(const float* __restrict__ le,
                                               const float* __restrict__ ce,
                                               const float* __restrict__ gamma,
                                               const float* __restrict__ beta,
                                               const int* __restrict__ cur) {
    const int y = blockIdx.y;
    const int h = blockIdx.x * 256 + threadIdx.x;
    if (y < Bz) {
        const float* p = g_partial + (long long)(y * SLABS_PER_B) * Hz + h;
        float s = 0.f;
        #pragma unroll 8
        for (int kk = 0; kk < SLABS_PER_B; ++kk) s += p[(long long)kk * Hz];
        const int cl = *cur;
        g_qin[y * Hz + h] = le[cl * Hz + h] + gamma[h] * (s * (1.0f / Sz)) + beta[h];
    } else {
        const int e = y - Bz;
        g_lf[e * Hz + h] = le[e * Hz + h] + ce[e * Hz + h];
    }
}

// ============================================================
// K3: fused q/k GEMV, split-K over 4 chunks, 2 j-rows per warp,
// f32x2 packed FMA. Blocks [0,512): k-type; [512,1024): q-type.
// ============================================================
template <int NE>
__device__ __forceinline__ void k3_body(const float* __restrict__ W,
                                        const float* __restrict__ xsrc,
                                        float* __restrict__ part,
                                        int c, int jbase) {
    __shared__ float xs[Ez * CH]; // 32 KB (upper part unused for NE=4)
    const int tid = threadIdx.x, warp = tid >> 5, lane = tid & 31;

    for (int i = tid; i < NE * (CH / 4); i += 256) {
        const int e = i >> 7, f = i & 127;
        ((float4*)xs)[i] = ((const float4*)xsrc)[e * (Hz / 4) + c * (CH / 4) + f];
    }
    __syncthreads();

    const int j0 = jbase + warp * JW;
    const ulonglong2* w0 = (const ulonglong2*)(W + (long long)(j0 + 0) * Hz + c * CH);
    const ulonglong2* w1 = (const ulonglong2*)(W + (long long)(j0 + 1) * Hz + c * CH);
    const ulonglong2* xv = (const ulonglong2*)xs;

    unsigned long long acc0[NE], acc1[NE];
    #pragma unroll
    for (int e = 0; e < NE; ++e) { acc0[e] = 0ull; acc1[e] = 0ull; }

    #pragma unroll
    for (int i = 0; i < 4; ++i) {
        const int f = i * 32 + lane;
        ulonglong2 a0 = w0[f];
        ulonglong2 a1 = w1[f];
        #pragma unroll
        for (int e = 0; e < NE; ++e) {
            ulonglong2 x2 = xv[e * 128 + f];
            FMA2(acc0[e], a0.x, x2.x);
            FMA2(acc0[e], a0.y, x2.y);
            FMA2(acc1[e], a1.x, x2.x);
            FMA2(acc1[e], a1.y, x2.y);
        }
    }

    #pragma unroll
    for (int e = 0; e < NE; ++e) {
        float v0 = unpack_sum(acc0[e]);
        float v1 = unpack_sum(acc1[e]);
        #pragma unroll
        for (int o = 16; o; o >>= 1) {
            v0 += __shfl_down_sync(0xffffffffu, v0, o);
            v1 += __shfl_down_sync(0xffffffffu, v1, o);
        }
        if (lane == 0) {
            part[(long long)c * NE * Hz + e * Hz + j0]     = v0;
            part[(long long)c * NE * Hz + e * Hz + j0 + 1] = v1;
        }
    }
}

__global__ __launch_bounds__(256, 2) void k3_qk(const float* __restrict__ Wq,
                                                const float* __restrict__ Wk) {
    const int bid = blockIdx.x;
    if (bid < K3_KBLOCKS) {
        const int c = bid & (NCH - 1);
        const int jbase = (bid >> 2) * JB;
        k3_body<Ez>(Wk, g_lf, g_kpart, c, jbase);
    } else {
        const int lb = bid - K3_KBLOCKS;
        const int c = lb & (NCH - 1);
        const int jbase = (lb >> 2) * JB;
        k3_body<Bz>(Wq, g_qin, g_qpart, c, jbase);
    }
}

// ============================================================
// K3b: sum the 4 split-K partials + bias -> g_k, g_q.
// 40960 outputs: first 32768 are k, rest are q.
// ============================================================
__global__ __launch_bounds__(256) void k3b_reduce(const float* __restrict__ bq,
                                                  const float* __restrict__ bk) {
    const int idx = blockIdx.x * 256 + threadIdx.x;
    if (idx < Ez * Hz) {
        const int j = idx & (Hz - 1);
        float s = bk[j];
        #pragma unroll
        for (int c = 0; c < NCH; ++c) s += g_kpart[c * Ez * Hz + idx];
        g_k[idx] = s;
    } else {
        const int r = idx - Ez * Hz;
        const int j = r & (Hz - 1);
        float s = bq[j];
        #pragma unroll
        for (int c = 0; c < NCH; ++c) s += g_qpart[c * Bz * Hz + r];
        g_q[r] = s;
    }
}

// ============================================================
// K4: attention dots, spatial bias, folded edge bias, softmax,
// KL routing loss, argmax, output writes. Single block.
// ============================================================
__global__ __launch_bounds__(512) void k4_final(const float* __restrict__ sp,
                                                const float* __restrict__ ee,
                                                const int* __restrict__ cur,
                                                const int* __restrict__ avail,
                                                float* __restrict__ out,
                                                int out_size) {
    __shared__ float att[Bz * Ez];
    __shared__ float u[EDz];
    __shared__ float ebias[Ez];
    __shared__ float sc[Bz * Ez];
    const int tid = threadIdx.x, warp = tid >> 5, lane = tid & 31;
    const int cl = *cur;

    // folded edge vector: u = sum_i avail_i*(i!=cl)/max(|i-cl|,1) * edge[i]
    {
        float uv = 0.f;
        #pragma unroll
        for (int i = 0; i < Ez; ++i) {
            if (avail[i] != 0 && i != cl) {
                int d = i > cl ? i - cl : cl - i;
                if (d < 1) d = 1;
                uv += (1.0f / (float)d) * ee[i * EDz + tid];
            }
        }
        u[tid] = uv;
    }

    // attention[b][e] = q[b]·k[e] / sqrt(H)
    const float iscale = 1.0f / sqrtf((float)Hz);
    for (int d = warp; d < Bz * Ez; d += 16) {
        const int b = d >> 4, e = d & 15;
        const float4* qq = (const float4*)(g_q + b * Hz);
        const float4* kk = (const float4*)(g_k + e * Hz);
        float a = 0.f;
        for (int i = lane; i < Hz / 4; i += 32) {
            float4 qv = qq[i];
            float4 kv = kk[i];
            a += qv.x * kv.x + qv.y * kv.y + qv.z * kv.z + qv.w * kv.w;
        }
        #pragma unroll
        for (int o = 16; o; o >>= 1) a += __shfl_down_sync(0xffffffffu, a, o);
        if (lane == 0) att[d] = a * iscale;
    }
    __syncthreads();

    // edge_bias[j] = u · edge[j]
    if (warp < Ez) {
        const int j = warp;
        float a = 0.f;
        for (int i = lane; i < EDz; i += 32) a += u[i] * ee[j * EDz + i];
        #pragma unroll
        for (int o = 16; o; o >>= 1) a += __shfl_down_sync(0xffffffffu, a, o);
        if (lane == 0) ebias[j] = a;
    }
    __syncthreads();

    if (tid < Bz * Ez) {
        const int e = tid & 15;
        int d = e > cl ? e - cl : cl - e;
        float s = att[tid] + sp[d] + ebias[e];
        sc[tid] = (avail[e] != 0) ? s : NEG_INF;
    }
    __syncthreads();

    if (tid == 0) {
        float navail = 0.f;
        for (int e = 0; e < Ez; ++e) navail += (avail[e] != 0) ? 1.0f : 0.0f;
        const float t = 1.0f / navail;
        const float logt = logf(t);
        float probs[Bz * Ez];
        float kl = 0.f;
        for (int b = 0; b < Bz; ++b) {
            float mx = -3.4e38f;
            for (int e = 0; e < Ez; ++e) mx = fmaxf(mx, sc[b * Ez + e]);
            float sum = 0.f;
            float ex[Ez];
            for (int e = 0; e < Ez; ++e) { ex[e] = expf(sc[b * Ez + e] - mx); sum += ex[e]; }
            const float inv = 1.0f / sum;
            for (int e = 0; e < Ez; ++e) {
                float p = ex[e] * inv;
                probs[b * Ez + e] = p;
                float ps = fmaxf(p, 1e-10f);
                kl += t * (logt - logf(ps));
            }
        }
        const float loss = (kl / (float)Bz) * 0.01f;
        int ai = 0; float av = probs[0];
        for (int e = 1; e < Ez; ++e) if (probs[e] > av) { av = probs[e]; ai = e; }

        if (out_size >= 66) {
            out[0] = loss;
            for (int i = 0; i < Bz * Ez; ++i) out[1 + i] = probs[i];
            out[65] = (float)ai;
            for (int i = 66; i < out_size; ++i) out[i] = 0.f;
        } else if (out_size == 65) {
            out[0] = loss;
            for (int i = 0; i < Bz * Ez; ++i) out[1 + i] = probs[i];
        } else if (out_size == 64) {
            for (int i = 0; i < Bz * Ez; ++i) out[i] = probs[i];
        } else if (out_size >= 1) {
            out[0] = loss;
            for (int i = 1; i < out_size && i <= Bz * Ez; ++i) out[i] = probs[i - 1];
        }
    }
}

extern "C" void kernel_launch(void* const* d_in, const int* in_sizes, int n_in,
                              void* d_out, int out_size) {
    const float* hs = (const float*)d_in[0];
    const float* le = (const float*)d_in[1];
    const float* ce = (const float*)d_in[2];
    const float* sp = (const float*)d_in[3];
    const float* ee = (const float*)d_in[4];
    const float* g  = (const float*)d_in[5];
    const float* be = (const float*)d_in[6];
    const float* Wq = (const float*)d_in[7];
    const float* bq = (const float*)d_in[8];
    const float* Wk = (const float*)d_in[9];
    const float* bk = (const float*)d_in[10];
    // d_in[11], d_in[12] = Wv, bv: dead in reference, intentionally unread
    const int* cl = (const int*)d_in[13];
    const int* av = (const int*)d_in[14];
    float* out = (float*)d_out;

    k1_ln_mean<<<K1_BLOCKS, 128>>>(hs);
    k2_prep<<<dim3(Hz / 256, Bz + Ez), 256>>>(le, ce, g, be, cl);
    k3_qk<<<K3_BLOCKS, 256>>>(Wq, Wk);
    k3b_reduce<<<(Ez * Hz + Bz * Hz) / 256, 256>>>(bq, bk);
    k4_final<<<1, 512>>>(sp, ee, cl, av, out, out_size);
}

// round 13
// speedup vs baseline: 1.4570x; 1.1884x over previous
#include <cuda_runtime.h>
#include <math.h>

#define Bz 4
#define Sz 4096
#define Hz 2048
#define Ez 16
#define EDz 512
#define LN_EPS 1e-5f
#define NEG_INF -1e9f

// ---- k1: single-wave config: 148 SMs x 3 blocks = 444 ----
#define K1_BPB 111                    /* blocks per batch */
#define K1_BLOCKS (Bz * K1_BPB)       /* 444 */
#define K1_RPB 37                     /* ceil(4096/111) rows per block */

// ---- k3 config: split-K GEMV, 2 j per warp, chunk=512 floats ----
#define CH 512
#define NCH 4
#define JW 2
#define K3_WARPS 8
#define JB (K3_WARPS * JW)          /* 16 j per block */
#define JG (Hz / JB)                /* 128 j-groups per type */
#define K3_KBLOCKS (JG * NCH)       /* 512 */
#define K3_BLOCKS (2 * K3_KBLOCKS)  /* 1024 */

// ---- scratch (16B-aligned: these are all vector-cast) ----
__device__ __align__(16) float g_partial[K1_BLOCKS * Hz]; // LN-mean partial slabs
__device__ __align__(16) float g_qin[Bz * Hz];            // query_input
__device__ __align__(16) float g_lf[Ez * Hz];             // layer_features = le + ce
__device__ __align__(16) float g_qpart[NCH * Bz * Hz];    // q split-K partials
__device__ __align__(16) float g_kpart[NCH * Ez * Hz];    // k split-K partials
__device__ __align__(16) float g_q[Bz * Hz];
__device__ __align__(16) float g_k[Ez * Hz];
__device__ int g_cnt[2 * JG];                             // last-block counters (self-resetting)

// packed fp32x2 FMA (FFMA2 — PTX-only on sm_103a)
#define FMA2(acc, a, b) \
    asm("fma.rn.f32x2 %0, %1, %2, %0;" : "+l"(acc) : "l"(a), "l"(b))

__device__ __forceinline__ float unpack_sum(unsigned long long v) {
    return __uint_as_float((unsigned)(v & 0xffffffffull)) +
           __uint_as_float((unsigned)(v >> 32));
}

// xor-butterfly all-reduce (redux.sync.add.f32 is NOT supported on sm_103)
__device__ __forceinline__ float warp_allreduce_add(float v) {
    #pragma unroll
    for (int o = 16; o; o >>= 1) v += __shfl_xor_sync(0xffffffffu, v, o);
    return v;
}

// ============================================================
// K1: warp-per-row fused LayerNorm + mean-over-S accumulation.
// 444 blocks = one full wave at occ 3.
// ============================================================
__global__ __launch_bounds__(128, 3) void k1_ln_mean(const float* __restrict__ x) {
    const int tid = threadIdx.x, lane = tid & 31, warp = tid >> 5;
    const int batch = blockIdx.x / K1_BPB;
    const int lb = blockIdx.x % K1_BPB;
    const int r0 = lb * K1_RPB;
    int r1 = r0 + K1_RPB; if (r1 > Sz) r1 = Sz;

    float4 acc[16];
    #pragma unroll
    for (int i = 0; i < 16; ++i) acc[i] = make_float4(0.f, 0.f, 0.f, 0.f);

    for (int r = r0 + warp; r < r1; r += 4) {
        const float4* row = (const float4*)(x + ((long long)batch * Sz + r) * Hz);
        float4 v[16];
        #pragma unroll
        for (int i = 0; i < 16; ++i) v[i] = __ldcs(&row[i * 32 + lane]);

        float s = 0.f, ss = 0.f;
        #pragma unroll
        for (int i = 0; i < 16; ++i) {
            s  += v[i].x + v[i].y + v[i].z + v[i].w;
            ss += v[i].x * v[i].x + v[i].y * v[i].y
                + v[i].z * v[i].z + v[i].w * v[i].w;
        }
        #pragma unroll
        for (int o = 16; o; o >>= 1) {
            s  += __shfl_xor_sync(0xffffffffu, s,  o);
            ss += __shfl_xor_sync(0xffffffffu, ss, o);
        }
        const float mu  = s * (1.0f / Hz);
        const float var = ss * (1.0f / Hz) - mu * mu;
        const float rs  = rsqrtf(var + LN_EPS);
        #pragma unroll
        for (int i = 0; i < 16; ++i) {
            acc[i].x += (v[i].x - mu) * rs;
            acc[i].y += (v[i].y - mu) * rs;
            acc[i].z += (v[i].z - mu) * rs;
            acc[i].w += (v[i].w - mu) * rs;
        }
    }

    __shared__ __align__(16) float4 red[4 * 512]; // 32 KB
    #pragma unroll
    for (int i = 0; i < 16; ++i) red[warp * 512 + i * 32 + lane] = acc[i];
    __syncthreads();

    float4* gp = (float4*)(g_partial + (long long)blockIdx.x * Hz);
    for (int t = tid; t < 512; t += 128) {
        float4 a = red[t], b = red[512 + t], c = red[1024 + t], d = red[1536 + t];
        gp[t] = make_float4(a.x + b.x + c.x + d.x, a.y + b.y + c.y + d.y,
                            a.z + b.z + c.z + d.z, a.w + b.w + c.w + d.w);
    }
}

// ============================================================
// K2: reduce 111 partial slabs/batch -> g_qin; build g_lf.
// grid (Hz/256, Bz + Ez)
// ============================================================
__global__ __launch_bounds__(256) void k2_prep(const float* __restrict__ le,
                                               const float* __restrict__ ce,
                                               const float* __restrict__ gamma,
                                               const float* __restrict__ beta,
                                               const int* __restrict__ cur) {
    const int y = blockIdx.y;
    const int h = blockIdx.x * 256 + threadIdx.x;
    if (y < Bz) {
        const float* p = g_partial + (long long)(y * K1_BPB) * Hz + h;
        float s = 0.f;
        #pragma unroll 8
        for (int kk = 0; kk < K1_BPB; ++kk) s += p[(long long)kk * Hz];
        const int cl = *cur;
        g_qin[y * Hz + h] = le[cl * Hz + h] + gamma[h] * (s * (1.0f / Sz)) + beta[h];
    } else {
        const int e = y - Bz;
        g_lf[e * Hz + h] = le[e * Hz + h] + ce[e * Hz + h];
    }
}

// ============================================================
// K3: fused q/k GEMV, split-K over 4 chunks, 2 j-rows per warp,
// f32x2 FMA. The last chunk-block per j-group finalizes
// (sums partials in fixed order + bias) — no separate kernel.
// ============================================================
template <int NE>
__device__ __forceinline__ void k3_body(const float* __restrict__ W,
                                        const float* __restrict__ xsrc,
                                        float* __restrict__ part,
                                        const float* __restrict__ bias,
                                        float* __restrict__ dst,
                                        int* __restrict__ cnt,
                                        int c, int jg) {
    // 16B alignment is mandatory: xs is accessed via float4/ulonglong2.
    __shared__ __align__(16) float xs[Ez * CH]; // 32 KB (NE=4 uses a quarter)
    __shared__ int slast;
    const int tid = threadIdx.x, warp = tid >> 5, lane = tid & 31;
    const int jbase = jg * JB;

    for (int i = tid; i < NE * (CH / 4); i += 256) {
        const int e = i >> 7, f = i & 127;
        ((float4*)xs)[i] = ((const float4*)xsrc)[e * (Hz / 4) + c * (CH / 4) + f];
    }
    __syncthreads();

    const int j0 = jbase + warp * JW;
    const ulonglong2* w0 = (const ulonglong2*)(W + (long long)(j0 + 0) * Hz + c * CH);
    const ulonglong2* w1 = (const ulonglong2*)(W + (long long)(j0 + 1) * Hz + c * CH);
    const ulonglong2* xv = (const ulonglong2*)xs;

    unsigned long long acc0[NE], acc1[NE];
    #pragma unroll
    for (int e = 0; e < NE; ++e) { acc0[e] = 0ull; acc1[e] = 0ull; }

    #pragma unroll
    for (int i = 0; i < 4; ++i) {
        const int f = i * 32 + lane;
        ulonglong2 a0 = w0[f];
        ulonglong2 a1 = w1[f];
        #pragma unroll
        for (int e = 0; e < NE; ++e) {
            ulonglong2 x2 = xv[e * 128 + f];
            FMA2(acc0[e], a0.x, x2.x);
            FMA2(acc0[e], a0.y, x2.y);
            FMA2(acc1[e], a1.x, x2.x);
            FMA2(acc1[e], a1.y, x2.y);
        }
    }

    #pragma unroll
    for (int e = 0; e < NE; ++e) {
        float v0 = unpack_sum(acc0[e]);
        float v1 = unpack_sum(acc1[e]);
        #pragma unroll
        for (int o = 16; o; o >>= 1) {
            v0 += __shfl_down_sync(0xffffffffu, v0, o);
            v1 += __shfl_down_sync(0xffffffffu, v1, o);
        }
        if (lane == 0) {
            part[(long long)c * NE * Hz + e * Hz + j0]     = v0;
            part[(long long)c * NE * Hz + e * Hz + j0 + 1] = v1;
        }
    }

    // ---- last-block finalize for this j-group ----
    __threadfence();
    __syncthreads();
    if (tid == 0) slast = atomicAdd(cnt + jg, 1);
    __syncthreads();
    if (slast == NCH - 1) {
        __threadfence();
        if (tid < NE * JB) {
            const int e = tid / JB, jj = tid % JB;
            const int j = jbase + jj;
            float s = bias[j];
            #pragma unroll
            for (int cc = 0; cc < NCH; ++cc)
                s += part[(long long)cc * NE * Hz + e * Hz + j];
            dst[e * Hz + j] = s;
        }
        if (tid == 0) cnt[jg] = 0; // self-reset for graph replay
    }
}

__global__ __launch_bounds__(256, 2) void k3_qk(const float* __restrict__ Wq,
                                                const float* __restrict__ Wk,
                                                const float* __restrict__ bq,
                                                const float* __restrict__ bk) {
    const int bid = blockIdx.x;
    if (bid < K3_KBLOCKS) {
        k3_body<Ez>(Wk, g_lf, g_kpart, bk, g_k, g_cnt, bid & (NCH - 1), bid >> 2);
    } else {
        const int lb = bid - K3_KBLOCKS;
        k3_body<Bz>(Wq, g_qin, g_qpart, bq, g_q, g_cnt + JG, lb & (NCH - 1), lb >> 2);
    }
}

// ============================================================
// K4: attention dots, spatial bias, folded edge bias, softmax,
// KL routing loss, argmax, output writes. Single block.
// ============================================================
__global__ __launch_bounds__(512) void k4_final(const float* __restrict__ sp,
                                                const float* __restrict__ ee,
                                                const int* __restrict__ cur,
                                                const int* __restrict__ avail,
                                                float* __restrict__ out,
                                                int out_size) {
    __shared__ float att[Bz * Ez];
    __shared__ float u[EDz];
    __shared__ float ebias[Ez];
    __shared__ float sc[Bz * Ez];
    const int tid = threadIdx.x, warp = tid >> 5, lane = tid & 31;
    const int cl = *cur;

    // folded edge vector: u = sum_i avail_i*(i!=cl)/max(|i-cl|,1) * edge[i]
    {
        float uv = 0.f;
        #pragma unroll
        for (int i = 0; i < Ez; ++i) {
            if (avail[i] != 0 && i != cl) {
                int d = i > cl ? i - cl : cl - i;
                if (d < 1) d = 1;
                uv += (1.0f / (float)d) * ee[i * EDz + tid];
            }
        }
        u[tid] = uv;
    }

    // attention[b][e] = q[b]·k[e] / sqrt(H)
    const float iscale = 1.0f / sqrtf((float)Hz);
    for (int d = warp; d < Bz * Ez; d += 16) {
        const int b = d >> 4, e = d & 15;
        const float4* qq = (const float4*)(g_q + b * Hz);
        const float4* kk = (const float4*)(g_k + e * Hz);
        float a = 0.f;
        for (int i = lane; i < Hz / 4; i += 32) {
            float4 qv = qq[i];
            float4 kv = kk[i];
            a += qv.x * kv.x + qv.y * kv.y + qv.z * kv.z + qv.w * kv.w;
        }
        a = warp_allreduce_add(a);
        if (lane == 0) att[d] = a * iscale;
    }
    __syncthreads();

    // edge_bias[j] = u · edge[j]
    if (warp < Ez) {
        const int j = warp;
        float a = 0.f;
        for (int i = lane; i < EDz; i += 32) a += u[i] * ee[j * EDz + i];
        a = warp_allreduce_add(a);
        if (lane == 0) ebias[j] = a;
    }
    __syncthreads();

    if (tid < Bz * Ez) {
        const int e = tid & 15;
        int d = e > cl ? e - cl : cl - e;
        float s = att[tid] + sp[d] + ebias[e];
        sc[tid] = (avail[e] != 0) ? s : NEG_INF;
    }
    __syncthreads();

    if (tid == 0) {
        float navail = 0.f;
        for (int e = 0; e < Ez; ++e) navail += (avail[e] != 0) ? 1.0f : 0.0f;
        const float t = 1.0f / navail;
        const float logt = logf(t);
        float probs[Bz * Ez];
        float kl = 0.f;
        for (int b = 0; b < Bz; ++b) {
            float mx = -3.4e38f;
            for (int e = 0; e < Ez; ++e) mx = fmaxf(mx, sc[b * Ez + e]);
            float sum = 0.f;
            float ex[Ez];
            for (int e = 0; e < Ez; ++e) { ex[e] = expf(sc[b * Ez + e] - mx); sum += ex[e]; }
            const float inv = 1.0f / sum;
            for (int e = 0; e < Ez; ++e) {
                float p = ex[e] * inv;
                probs[b * Ez + e] = p;
                float ps = fmaxf(p, 1e-10f);
                kl += t * (logt - logf(ps));
            }
        }
        const float loss = (kl / (float)Bz) * 0.01f;
        int ai = 0; float av = probs[0];
        for (int e = 1; e < Ez; ++e) if (probs[e] > av) { av = probs[e]; ai = e; }

        if (out_size >= 66) {
            out[0] = loss;
            for (int i = 0; i < Bz * Ez; ++i) out[1 + i] = probs[i];
            out[65] = (float)ai;
            for (int i = 66; i < out_size; ++i) out[i] = 0.f;
        } else if (out_size == 65) {
            out[0] = loss;
            for (int i = 0; i < Bz * Ez; ++i) out[1 + i] = probs[i];
        } else if (out_size == 64) {
            for (int i = 0; i < Bz * Ez; ++i) out[i] = probs[i];
        } else if (out_size >= 1) {
            out[0] = loss;
            for (int i = 1; i < out_size && i <= Bz * Ez; ++i) out[i] = probs[i - 1];
        }
    }
}

extern "C" void kernel_launch(void* const* d_in, const int* in_sizes, int n_in,
                              void* d_out, int out_size) {
    const float* hs = (const float*)d_in[0];
    const float* le = (const float*)d_in[1];
    const float* ce = (const float*)d_in[2];
    const float* sp = (const float*)d_in[3];
    const float* ee = (const float*)d_in[4];
    const float* g  = (const float*)d_in[5];
    const float* be = (const float*)d_in[6];
    const float* Wq = (const float*)d_in[7];
    const float* bq = (const float*)d_in[8];
    const float* Wk = (const float*)d_in[9];
    const float* bk = (const float*)d_in[10];
    // d_in[11], d_in[12] = Wv, bv: dead in reference, intentionally unread
    const int* cl = (const int*)d_in[13];
    const int* av = (const int*)d_in[14];
    float* out = (float*)d_out;

    k1_ln_mean<<<K1_BLOCKS, 128>>>(hs);
    k2_prep<<<dim3(Hz / 256, Bz + Ez), 256>>>(le, ce, g, be, cl);
    k3_qk<<<K3_BLOCKS, 256>>>(Wq, Wk, bq, bk);
    k4_final<<<1, 512>>>(sp, ee, cl, av, out, out_size);
}

// round 15
// speedup vs baseline: 1.5438x; 1.0596x over previous
#include <cuda_runtime.h>
#include <math.h>

#define Bz 4
#define Sz 4096
#define Hz 2048
#define Ez 16
#define EDz 512
#define LN_EPS 1e-5f
#define NEG_INF -1e9f

// ---- k1: single-wave config: 148 SMs x 3 blocks = 444 ----
#define K1_BPB 111                    /* blocks per batch */
#define K1_BLOCKS (Bz * K1_BPB)       /* 444 */
#define K1_RPB 37                     /* ceil(4096/111) rows per block */

// ---- k3 config: split-K GEMV, 2 j per warp, chunk=512 floats ----
#define CH 512
#define NCH 4
#define JW 2
#define K3_WARPS 8
#define JB (K3_WARPS * JW)          /* 16 j per block */
#define JG (Hz / JB)                /* 128 j-groups per type */
#define K3_KBLOCKS (JG * NCH)       /* 512 */
#define K3_BLOCKS (2 * K3_KBLOCKS)  /* 1024 */

// ---- scratch (16B-aligned: these are all vector-cast) ----
__device__ __align__(16) float g_partial[K1_BLOCKS * Hz]; // LN-mean partial slabs
__device__ __align__(16) float g_qin[Bz * Hz];            // query_input
__device__ __align__(16) float g_lf[Ez * Hz];             // layer_features = le + ce
__device__ __align__(16) float g_qpart[NCH * Bz * Hz];    // q split-K partials
__device__ __align__(16) float g_kpart[NCH * Ez * Hz];    // k split-K partials
__device__ __align__(16) float g_q[Bz * Hz];
__device__ __align__(16) float g_k[Ez * Hz];
__device__ int g_cnt[2 * JG];                             // last-block counters (self-resetting)

// packed fp32x2 FMA (FFMA2 — PTX-only on sm_103a)
#define FMA2(acc, a, b) \
    asm("fma.rn.f32x2 %0, %1, %2, %0;" : "+l"(acc) : "l"(a), "l"(b))

__device__ __forceinline__ float unpack_sum(unsigned long long v) {
    return __uint_as_float((unsigned)(v & 0xffffffffull)) +
           __uint_as_float((unsigned)(v >> 32));
}

// xor-butterfly all-reduce (redux.sync.add.f32 is NOT supported on sm_103)
__device__ __forceinline__ float warp_allreduce_add(float v) {
    #pragma unroll
    for (int o = 16; o; o >>= 1) v += __shfl_xor_sync(0xffffffffu, v, o);
    return v;
}

// ============================================================
// K1: warp-per-row fused LayerNorm + mean-over-S accumulation.
// 444 blocks = one full wave at occ 3.
// ============================================================
__global__ __launch_bounds__(128, 3) void k1_ln_mean(const float* __restrict__ x) {
    const int tid = threadIdx.x, lane = tid & 31, warp = tid >> 5;
    const int batch = blockIdx.x / K1_BPB;
    const int lb = blockIdx.x % K1_BPB;
    const int r0 = lb * K1_RPB;
    int r1 = r0 + K1_RPB; if (r1 > Sz) r1 = Sz;

    float4 acc[16];
    #pragma unroll
    for (int i = 0; i < 16; ++i) acc[i] = make_float4(0.f, 0.f, 0.f, 0.f);

    for (int r = r0 + warp; r < r1; r += 4) {
        const float4* row = (const float4*)(x + ((long long)batch * Sz + r) * Hz);
        float4 v[16];
        #pragma unroll
        for (int i = 0; i < 16; ++i) v[i] = __ldcs(&row[i * 32 + lane]);

        float s = 0.f, ss = 0.f;
        #pragma unroll
        for (int i = 0; i < 16; ++i) {
            s  += v[i].x + v[i].y + v[i].z + v[i].w;
            ss += v[i].x * v[i].x + v[i].y * v[i].y
                + v[i].z * v[i].z + v[i].w * v[i].w;
        }
        #pragma unroll
        for (int o = 16; o; o >>= 1) {
            s  += __shfl_xor_sync(0xffffffffu, s,  o);
            ss += __shfl_xor_sync(0xffffffffu, ss, o);
        }
        const float mu  = s * (1.0f / Hz);
        const float var = ss * (1.0f / Hz) - mu * mu;
        const float rs  = rsqrtf(var + LN_EPS);
        #pragma unroll
        for (int i = 0; i < 16; ++i) {
            acc[i].x += (v[i].x - mu) * rs;
            acc[i].y += (v[i].y - mu) * rs;
            acc[i].z += (v[i].z - mu) * rs;
            acc[i].w += (v[i].w - mu) * rs;
        }
    }

    __shared__ __align__(16) float4 red[4 * 512]; // 32 KB
    #pragma unroll
    for (int i = 0; i < 16; ++i) red[warp * 512 + i * 32 + lane] = acc[i];
    __syncthreads();

    float4* gp = (float4*)(g_partial + (long long)blockIdx.x * Hz);
    for (int t = tid; t < 512; t += 128) {
        float4 a = red[t], b = red[512 + t], c = red[1024 + t], d = red[1536 + t];
        gp[t] = make_float4(a.x + b.x + c.x + d.x, a.y + b.y + c.y + d.y,
                            a.z + b.z + c.z + d.z, a.w + b.w + c.w + d.w);
    }
}

// ============================================================
// K2: reduce 111 partial slabs/batch -> g_qin; build g_lf.
// grid (Hz/256, Bz + Ez)
// ============================================================
__global__ __launch_bounds__(256) void k2_prep(const float* __restrict__ le,
                                               const float* __restrict__ ce,
                                               const float* __restrict__ gamma,
                                               const float* __restrict__ beta,
                                               const int* __restrict__ cur) {
    const int y = blockIdx.y;
    const int h = blockIdx.x * 256 + threadIdx.x;
    if (y < Bz) {
        const float* p = g_partial + (long long)(y * K1_BPB) * Hz + h;
        float s = 0.f;
        #pragma unroll 8
        for (int kk = 0; kk < K1_BPB; ++kk) s += p[(long long)kk * Hz];
        const int cl = *cur;
        g_qin[y * Hz + h] = le[cl * Hz + h] + gamma[h] * (s * (1.0f / Sz)) + beta[h];
    } else {
        const int e = y - Bz;
        g_lf[e * Hz + h] = le[e * Hz + h] + ce[e * Hz + h];
    }
}

// ============================================================
// K3: fused q/k GEMV, split-K over 4 chunks, 2 j-rows per warp,
// f32x2 FMA. The last chunk-block per j-group finalizes
// (sums partials in fixed order + bias) — no separate kernel.
// ============================================================
template <int NE>
__device__ __forceinline__ void k3_body(const float* __restrict__ W,
                                        const float* __restrict__ xsrc,
                                        float* __restrict__ part,
                                        const float* __restrict__ bias,
                                        float* __restrict__ dst,
                                        int* __restrict__ cnt,
                                        int c, int jg) {
    // 16B alignment is mandatory: xs is accessed via float4/ulonglong2.
    __shared__ __align__(16) float xs[Ez * CH]; // 32 KB (NE=4 uses a quarter)
    __shared__ int slast;
    const int tid = threadIdx.x, warp = tid >> 5, lane = tid & 31;
    const int jbase = jg * JB;

    for (int i = tid; i < NE * (CH / 4); i += 256) {
        const int e = i >> 7, f = i & 127;
        ((float4*)xs)[i] = ((const float4*)xsrc)[e * (Hz / 4) + c * (CH / 4) + f];
    }
    __syncthreads();

    const int j0 = jbase + warp * JW;
    const ulonglong2* w0 = (const ulonglong2*)(W + (long long)(j0 + 0) * Hz + c * CH);
    const ulonglong2* w1 = (const ulonglong2*)(W + (long long)(j0 + 1) * Hz + c * CH);
    const ulonglong2* xv = (const ulonglong2*)xs;

    unsigned long long acc0[NE], acc1[NE];
    #pragma unroll
    for (int e = 0; e < NE; ++e) { acc0[e] = 0ull; acc1[e] = 0ull; }

    #pragma unroll
    for (int i = 0; i < 4; ++i) {
        const int f = i * 32 + lane;
        ulonglong2 a0 = w0[f];
        ulonglong2 a1 = w1[f];
        #pragma unroll
        for (int e = 0; e < NE; ++e) {
            ulonglong2 x2 = xv[e * 128 + f];
            FMA2(acc0[e], a0.x, x2.x);
            FMA2(acc0[e], a0.y, x2.y);
            FMA2(acc1[e], a1.x, x2.x);
            FMA2(acc1[e], a1.y, x2.y);
        }
    }

    #pragma unroll
    for (int e = 0; e < NE; ++e) {
        float v0 = unpack_sum(acc0[e]);
        float v1 = unpack_sum(acc1[e]);
        #pragma unroll
        for (int o = 16; o; o >>= 1) {
            v0 += __shfl_down_sync(0xffffffffu, v0, o);
            v1 += __shfl_down_sync(0xffffffffu, v1, o);
        }
        if (lane == 0) {
            part[(long long)c * NE * Hz + e * Hz + j0]     = v0;
            part[(long long)c * NE * Hz + e * Hz + j0 + 1] = v1;
        }
    }

    // ---- last-block finalize for this j-group ----
    __threadfence();
    __syncthreads();
    if (tid == 0) slast = atomicAdd(cnt + jg, 1);
    __syncthreads();
    if (slast == NCH - 1) {
        __threadfence();
        if (tid < NE * JB) {
            const int e = tid / JB, jj = tid % JB;
            const int j = jbase + jj;
            float s = bias[j];
            #pragma unroll
            for (int cc = 0; cc < NCH; ++cc)
                s += part[(long long)cc * NE * Hz + e * Hz + j];
            dst[e * Hz + j] = s;
        }
        if (tid == 0) cnt[jg] = 0; // self-reset for graph replay
    }
}

__global__ __launch_bounds__(256, 2) void k3_qk(const float* __restrict__ Wq,
                                                const float* __restrict__ Wk,
                                                const float* __restrict__ bq,
                                                const float* __restrict__ bk) {
    const int bid = blockIdx.x;
    if (bid < K3_KBLOCKS) {
        k3_body<Ez>(Wk, g_lf, g_kpart, bk, g_k, g_cnt, bid & (NCH - 1), bid >> 2);
    } else {
        const int lb = bid - K3_KBLOCKS;
        k3_body<Bz>(Wq, g_qin, g_qpart, bq, g_q, g_cnt + JG, lb & (NCH - 1), lb >> 2);
    }
}

// ============================================================
// K4: attention dots, spatial bias, folded edge bias, softmax,
// KL routing loss, argmax, output writes. Single block,
// fully parallel epilogue (no single-thread transcendental tail).
// ============================================================
__global__ __launch_bounds__(512) void k4_final(const float* __restrict__ sp,
                                                const float* __restrict__ ee,
                                                const int* __restrict__ cur,
                                                const int* __restrict__ avail,
                                                float* __restrict__ out,
                                                int out_size) {
    __shared__ float att[Bz * Ez];
    __shared__ float u[EDz];
    __shared__ float ebias[Ez];
    __shared__ float sc[Bz * Ez];
    __shared__ float probs[Bz * Ez];
    __shared__ float klpart[2];
    __shared__ float s_loss;
    __shared__ int s_ai;
    const int tid = threadIdx.x, warp = tid >> 5, lane = tid & 31;
    const int cl = *cur;

    // folded edge vector: u = sum_i avail_i*(i!=cl)/max(|i-cl|,1) * edge[i]
    {
        float uv = 0.f;
        #pragma unroll
        for (int i = 0; i < Ez; ++i) {
            if (avail[i] != 0 && i != cl) {
                int d = i > cl ? i - cl : cl - i;
                if (d < 1) d = 1;
                uv += (1.0f / (float)d) * ee[i * EDz + tid];
            }
        }
        u[tid] = uv;
    }

    // attention[b][e] = q[b]·k[e] / sqrt(H)
    const float iscale = 1.0f / sqrtf((float)Hz);
    for (int d = warp; d < Bz * Ez; d += 16) {
        const int b = d >> 4, e = d & 15;
        const float4* qq = (const float4*)(g_q + b * Hz);
        const float4* kk = (const float4*)(g_k + e * Hz);
        float a = 0.f;
        #pragma unroll 4
        for (int i = lane; i < Hz / 4; i += 32) {
            float4 qv = qq[i];
            float4 kv = kk[i];
            a += qv.x * kv.x + qv.y * kv.y + qv.z * kv.z + qv.w * kv.w;
        }
        a = warp_allreduce_add(a);
        if (lane == 0) att[d] = a * iscale;
    }
    __syncthreads();

    // edge_bias[j] = u · edge[j]
    if (warp < Ez) {
        const int j = warp;
        float a = 0.f;
        for (int i = lane; i < EDz; i += 32) a += u[i] * ee[j * EDz + i];
        a = warp_allreduce_add(a);
        if (lane == 0) ebias[j] = a;
    }
    __syncthreads();

    // scores
    if (tid < Bz * Ez) {
        const int e = tid & 15;
        int d = e > cl ? e - cl : cl - e;
        float s = att[tid] + sp[d] + ebias[e];
        sc[tid] = (avail[e] != 0) ? s : NEG_INF;
    }
    __syncthreads();

    // ---- parallel softmax + KL over 64 threads (16-lane segments per batch) ----
    float navail = 0.f;
    #pragma unroll
    for (int e = 0; e < Ez; ++e) navail += (avail[e] != 0) ? 1.0f : 0.0f;
    const float t = 1.0f / navail;
    const float logt = logf(t);

    if (tid < Bz * Ez) {
        float s = sc[tid];
        float mx = s;
        #pragma unroll
        for (int o = 8; o; o >>= 1)
            mx = fmaxf(mx, __shfl_xor_sync(0xffffffffu, mx, o));
        float ex = expf(s - mx);
        float sum = ex;
        #pragma unroll
        for (int o = 8; o; o >>= 1)
            sum += __shfl_xor_sync(0xffffffffu, sum, o);
        float p = ex / sum;
        probs[tid] = p;
        float kle = t * (logt - logf(fmaxf(p, 1e-10f)));
        // reduce kle over full warp (32 lanes = 2 batches) then across 2 warps
        kle = warp_allreduce_add(kle);
        if (lane == 0) klpart[warp] = kle;
    }
    __syncthreads();

    if (tid == 0) {
        const float kl = klpart[0] + klpart[1];
        s_loss = (kl / (float)Bz) * 0.01f;
        int ai = 0; float av = probs[0];
        #pragma unroll
        for (int e = 1; e < Ez; ++e) if (probs[e] > av) { av = probs[e]; ai = e; }
        s_ai = ai;
    }
    __syncthreads();

    // ---- parallel output write ----
    if (out_size >= 66) {
        if (tid == 0) out[0] = s_loss;
        if (tid < Bz * Ez) out[1 + tid] = probs[tid];
        if (tid == 65) out[65] = (float)s_ai;
        for (int i = 66 + tid; i < out_size; i += 512) out[i] = 0.f;
    } else if (out_size == 65) {
        if (tid == 0) out[0] = s_loss;
        if (tid < Bz * Ez) out[1 + tid] = probs[tid];
    } else if (out_size == 64) {
        if (tid < Bz * Ez) out[tid] = probs[tid];
    } else if (out_size >= 1) {
        if (tid == 0) out[0] = s_loss;
        if (tid >= 1 && tid < out_size && tid <= Bz * Ez) out[tid] = probs[tid - 1];
    }
}

extern "C" void kernel_launch(void* const* d_in, const int* in_sizes, int n_in,
                              void* d_out, int out_size) {
    const float* hs = (const float*)d_in[0];
    const float* le = (const float*)d_in[1];
    const float* ce = (const float*)d_in[2];
    const float* sp = (const float*)d_in[3];
    const float* ee = (const float*)d_in[4];
    const float* g  = (const float*)d_in[5];
    const float* be = (const float*)d_in[6];
    const float* Wq = (const float*)d_in[7];
    const float* bq = (const float*)d_in[8];
    const float* Wk = (const float*)d_in[9];
    const float* bk = (const float*)d_in[10];
    // d_in[11], d_in[12] = Wv, bv: dead in reference, intentionally unread
    const int* cl = (const int*)d_in[13];
    const int* av = (const int*)d_in[14];
    float* out = (float*)d_out;

    k1_ln_mean<<<K1_BLOCKS, 128>>>(hs);
    k2_prep<<<dim3(Hz / 256, Bz + Ez), 256>>>(le, ce, g, be, cl);
    k3_qk<<<K3_BLOCKS, 256>>>(Wq, Wk, bq, bk);
    k4_final<<<1, 512>>>(sp, ee, cl, av, out, out_size);
}